// round 5
// baseline (speedup 1.0000x reference)
#include <cuda_runtime.h>
#include <cuda_bf16.h>

// PermutationClosedLayer via complement algebra:
//   out[s,r,o] = base[s,o] + sum_{p in comb5(r)} y[s,p,o]
//   y[s,p,o]   = sum_c x[s,p,c] * (W0-W1)[o,c]
//   base[s,o]  = sum_c (sum_p x[s,p,c]) * W1[o,c]
//
// 4 warps per sample, each emitting a 63-combination quarter of the
// lexicographic C(10,5) list (compile-time pruned nest). y/base computed
// once per sample (phase 1) and shared via smem.
// Block = 256 thr = 8 warps = 2 samples x 4 quarters. Grid = 2048.

#define NSAMPLES 4096
#define NSIZE 10
#define NCIN 32
#define NCOUT 32
#define NCOMB 252
#define THREADS 256
#define SAMPLES_PER_BLOCK 2

// Emit combinations r in [R0, R1) of the lexicographic nest. r is an
// unroll-constant at every leaf, so the range guard folds at compile time
// and chains feeding only out-of-range leaves are dead-code-eliminated.
template<int R0, int R1>
__device__ __forceinline__ void emit_range(float* __restrict__ op,
                                           const float (&y)[NSIZE], float base) {
    int r = 0;
#pragma unroll
    for (int i = 0; i <= 5; i++) {
        const float a1 = base + y[i];
#pragma unroll
        for (int j = i + 1; j <= 6; j++) {
            const float a2 = a1 + y[j];
#pragma unroll
            for (int k = j + 1; k <= 7; k++) {
                const float a3 = a2 + y[k];
#pragma unroll
                for (int l = k + 1; l <= 8; l++) {
                    const float a4 = a3 + y[l];
#pragma unroll
                    for (int m = l + 1; m <= 9; m++) {
                        if (r >= R0 && r < R1)
                            op[r * NCOUT] = a4 + y[m];
                        r++;
                    }
                }
            }
        }
    }
}

__global__ __launch_bounds__(THREADS, 6) void pcl_kernel(
    const float* __restrict__ x,    // [S, 10, 32]
    const float* __restrict__ W,    // [2, 32, 32]
    float* __restrict__ out)        // [S, 252, 32]
{
    __shared__ float wd_sm[NCIN][NCOUT];                         // (W0-W1)^T
    __shared__ float w1_sm[NCIN][NCOUT];                         // W1^T
    __shared__ float xs[SAMPLES_PER_BLOCK][NSIZE][NCIN];         // staged x rows
    __shared__ float ys[SAMPLES_PER_BLOCK][NSIZE + 1][NCIN];     // y[10] + base

    const int tid  = threadIdx.x;
    const int lane = tid & 31;
    const int w    = tid >> 5;          // warp 0..7
    const int smp  = w & 1;             // sample within block
    const int q    = w >> 1;            // combination quarter 0..3

    // Load W (transposed) into shared: wd[c][o], w1[c][o]
    for (int i = tid; i < NCOUT * NCIN; i += THREADS) {
        int o = i >> 5;
        int c = i & 31;
        float w0v = W[o * NCIN + c];
        float w1v = W[NCOUT * NCIN + o * NCIN + c];
        wd_sm[c][o] = w0v - w1v;
        w1_sm[c][o] = w1v;
    }

    const int s_base = blockIdx.x * SAMPLES_PER_BLOCK;

    // Warps 0-1 stage their sample's x rows (coalesced 128B per row)
    if (w < SAMPLES_PER_BLOCK) {
        const float* xp = x + (size_t)(s_base + w) * (NSIZE * NCIN);
#pragma unroll
        for (int p = 0; p < NSIZE; p++)
            xs[w][p][lane] = xp[p * NCIN + lane];
    }
    __syncthreads();   // W in smem + xs staged

    // Phase 1: warps 0-1 compute y[p][lane] and base[lane] for their sample
    if (w < SAMPLES_PER_BLOCK) {
        float y[NSIZE];
#pragma unroll
        for (int p = 0; p < NSIZE; p++) y[p] = 0.0f;
        float base = 0.0f;

#pragma unroll
        for (int c = 0; c < NCIN; c++) {
            const float wdv = wd_sm[c][lane];
            const float w1v = w1_sm[c][lane];
            float tot = 0.0f;
#pragma unroll
            for (int p = 0; p < NSIZE; p++) {
                const float xv = xs[w][p][c];   // smem broadcast
                y[p] = fmaf(xv, wdv, y[p]);
                tot += xv;
            }
            base = fmaf(tot, w1v, base);
        }
#pragma unroll
        for (int p = 0; p < NSIZE; p++)
            ys[w][p][lane] = y[p];
        ys[w][NSIZE][lane] = base;
    }
    __syncthreads();   // y/base visible to all warps

    // Phase 2: every warp emits its 63-combination quarter for its sample
    {
        float y[NSIZE];
#pragma unroll
        for (int p = 0; p < NSIZE; p++)
            y[p] = ys[smp][p][lane];
        const float base = ys[smp][NSIZE][lane];

        float* op = out + (size_t)(s_base + smp) * (size_t)(NCOMB * NCOUT) + lane;

        switch (q) {
            case 0:  emit_range<0,   63 >(op, y, base); break;
            case 1:  emit_range<63,  126>(op, y, base); break;
            case 2:  emit_range<126, 189>(op, y, base); break;
            default: emit_range<189, 252>(op, y, base); break;
        }
    }
}

extern "C" void kernel_launch(void* const* d_in, const int* in_sizes, int n_in,
                              void* d_out, int out_size) {
    const float* x = (const float*)d_in[0];
    const float* W = (const float*)d_in[1];
    // d_in[2] = splits : unused (compile-time lexicographic combination table)
    float* out = (float*)d_out;

    dim3 grid(NSAMPLES / SAMPLES_PER_BLOCK);   // 2048 blocks
    pcl_kernel<<<grid, THREADS>>>(x, W, out);
}

// round 6
// speedup vs baseline: 1.3728x; 1.3728x over previous
#include <cuda_runtime.h>
#include <cuda_bf16.h>

// PermutationClosedLayer via complement algebra:
//   out[s,r,o] = base[s,o] + sum_{p in comb5(r)} y[s,p,o]
//   y[s,p,o]   = sum_c x[s,p,c] * (W0-W1)[o,c]
//   base[s,o]  = sum_c (sum_p x[s,p,c]) * W1[o,c]
//
// 2 warps per sample, each emitting half of the lexicographic C(10,5) list:
//   half 0 = combinations containing position 0 (exactly the first 126),
//   half 1 = the rest (i >= 1).
// Each warp computes its own y/base (no phase split, no reg cap -> no spills).
// Block = 256 thr = 8 warps = 4 samples x 2 halves. Grid = 1024.

#define NSAMPLES 4096
#define NSIZE 10
#define NCIN 32
#define NCOUT 32
#define NCOMB 252
#define THREADS 256
#define SAMPLES_PER_BLOCK 4

// Emit the lexicographic nest restricted to i in [I0, I1]. r at each leaf is
// an unroll constant; chains feeding only skipped leaves are DCE'd.
template<int I0, int I1>
__device__ __forceinline__ void emit_half(float* __restrict__ op,
                                          const float (&y)[NSIZE], float base) {
    int r = 0;
#pragma unroll
    for (int i = 0; i <= 5; i++) {
#pragma unroll
        for (int j = i + 1; j <= 6; j++) {
#pragma unroll
            for (int k = j + 1; k <= 7; k++) {
#pragma unroll
                for (int l = k + 1; l <= 8; l++) {
#pragma unroll
                    for (int m = l + 1; m <= 9; m++) {
                        if (i >= I0 && i <= I1) {
                            float v = base + y[i] + y[j] + y[k] + y[l] + y[m];
                            op[r * NCOUT] = v;
                        }
                        r++;
                    }
                }
            }
        }
    }
}

__global__ __launch_bounds__(THREADS) void pcl_kernel(
    const float* __restrict__ x,    // [S, 10, 32]
    const float* __restrict__ W,    // [2, 32, 32]
    float* __restrict__ out)        // [S, 252, 32]
{
    __shared__ float wd_sm[NCIN][NCOUT];                    // (W0-W1)^T
    __shared__ float w1_sm[NCIN][NCOUT];                    // W1^T
    __shared__ float xs[SAMPLES_PER_BLOCK][NSIZE][NCIN];    // staged x rows

    const int tid  = threadIdx.x;
    const int lane = tid & 31;
    const int w    = tid >> 5;          // warp 0..7
    const int smp  = w >> 1;            // sample within block 0..3
    const int half = w & 1;             // 0: combos with pos 0, 1: rest

    // Load W (transposed) into shared: wd[c][o], w1[c][o]
    for (int i = tid; i < NCOUT * NCIN; i += THREADS) {
        int o = i >> 5;
        int c = i & 31;
        float w0v = W[o * NCIN + c];
        float w1v = W[NCOUT * NCIN + o * NCIN + c];
        wd_sm[c][o] = w0v - w1v;
        w1_sm[c][o] = w1v;
    }

    const int s_base = blockIdx.x * SAMPLES_PER_BLOCK;

    // Even warp of each pair stages the sample's x rows (coalesced 128B rows)
    if (half == 0) {
        const float* xp = x + (size_t)(s_base + smp) * (NSIZE * NCIN);
#pragma unroll
        for (int p = 0; p < NSIZE; p++)
            xs[smp][p][lane] = xp[p * NCIN + lane];
    }
    __syncthreads();   // W + xs visible

    // Each warp computes y[p] = x[s,p,:].wd[:,lane], base = total.w1[:,lane]
    float y[NSIZE];
#pragma unroll
    for (int p = 0; p < NSIZE; p++) y[p] = 0.0f;
    float base = 0.0f;

#pragma unroll
    for (int c = 0; c < NCIN; c++) {
        const float wdv = wd_sm[c][lane];
        const float w1v = w1_sm[c][lane];
        float tot = 0.0f;
#pragma unroll
        for (int p = 0; p < NSIZE; p++) {
            const float xv = xs[smp][p][c];   // smem broadcast
            y[p] = fmaf(xv, wdv, y[p]);
            tot += xv;
        }
        base = fmaf(tot, w1v, base);
    }

    // Emit this warp's half of the 252 combinations
    float* op = out + (size_t)(s_base + smp) * (size_t)(NCOMB * NCOUT) + lane;
    if (half == 0)
        emit_half<0, 0>(op, y, base);    // r in [0, 126)
    else
        emit_half<1, 5>(op, y, base);    // r in [126, 252)
}

extern "C" void kernel_launch(void* const* d_in, const int* in_sizes, int n_in,
                              void* d_out, int out_size) {
    const float* x = (const float*)d_in[0];
    const float* W = (const float*)d_in[1];
    // d_in[2] = splits : unused (compile-time lexicographic combination table)
    float* out = (float*)d_out;

    dim3 grid(NSAMPLES / SAMPLES_PER_BLOCK);   // 1024 blocks
    pcl_kernel<<<grid, THREADS>>>(x, W, out);
}